// round 12
// baseline (speedup 1.0000x reference)
#include <cuda_runtime.h>
#include <cuda_fp16.h>
#include <cstdint>

#define Bsz   8
#define Npts  16384
#define Spts  1024
#define Dfeat 256
#define CIN   512
#define CMID  256
#define COUT  256
#define CNT_INV (1.0f / (8.0f * 16384.0f))

// ---------------- scratch (device globals; no runtime allocation) ----------------
__device__ __align__(128) float g_p2t[Bsz * Spts * Dfeat];            // points2^T [B,S,D]
__device__ float g_w3[Bsz * Npts * 3];
__device__ int   g_i3[Bsz * Npts * 3];
__device__ __align__(128) __half g_xh[(size_t)Bsz * CIN * Npts];      // X [B,512,N] fp16
__device__ __align__(128) __half g_y0h[(size_t)Bsz * CMID * Npts];    // y0 [B,256,N] fp16
__device__ __align__(128) __half g_w0h[CMID * CIN], g_w0l[CMID * CIN];
__device__ __align__(128) __half g_w1h[COUT * CMID], g_w1l[COUT * CMID];
__device__ float g_sum0[CMID], g_sq0[CMID], g_sum1[COUT], g_sq1[COUT];
__device__ float g_a0[CMID], g_be0[CMID], g_a1[COUT], g_be1[COUT];

// ---------------- helpers ----------------
__device__ __forceinline__ uint32_t smem_u32(const void* p) {
    uint32_t a;
    asm("{ .reg .u64 t; cvta.to.shared.u64 t, %1; cvt.u32.u64 %0, t; }" : "=r"(a) : "l"(p));
    return a;
}
__device__ __forceinline__ void cp16(uint32_t dst, const void* src) {
    asm volatile("cp.async.cg.shared.global [%0], [%1], 16;" :: "r"(dst), "l"(src));
}
#define CP_COMMIT() asm volatile("cp.async.commit_group;" ::: "memory")
#define LDSM4(R, A) \
    asm volatile("ldmatrix.sync.aligned.m8n8.x4.shared.b16 {%0,%1,%2,%3}, [%4];" \
        : "=r"((R)[0]), "=r"((R)[1]), "=r"((R)[2]), "=r"((R)[3]) : "r"(A))
#define LDSM4T(R, A) \
    asm volatile("ldmatrix.sync.aligned.m8n8.x4.trans.shared.b16 {%0,%1,%2,%3}, [%4];" \
        : "=r"((R)[0]), "=r"((R)[1]), "=r"((R)[2]), "=r"((R)[3]) : "r"(A))
#define MMA16816(C, A, B0, B1) \
    asm volatile("mma.sync.aligned.m16n8k16.row.col.f32.f16.f16.f32 " \
        "{%0,%1,%2,%3}, {%4,%5,%6,%7}, {%8,%9}, {%0,%1,%2,%3};" \
        : "+f"((C)[0]), "+f"((C)[1]), "+f"((C)[2]), "+f"((C)[3]) \
        : "r"((A)[0]), "r"((A)[1]), "r"((A)[2]), "r"((A)[3]), "r"(B0), "r"(B1))

// ---------------- transpose points2 [B,D,S] -> [B,S,D] ----------------
__global__ void transpose_p2_kernel(const float* __restrict__ p2) {
    __shared__ float t[32][33];
    int b = blockIdx.z, s0 = blockIdx.x * 32, d0 = blockIdx.y * 32;
    int tx = threadIdx.x, ty = threadIdx.y;
    const float* src = p2 + (size_t)b * Dfeat * Spts;
#pragma unroll
    for (int j = 0; j < 32; j += 8)
        t[ty + j][tx] = src[(size_t)(d0 + ty + j) * Spts + s0 + tx];
    __syncthreads();
    float* dst = g_p2t + (size_t)b * Spts * Dfeat;
#pragma unroll
    for (int j = 0; j < 32; j += 8)
        dst[(size_t)(s0 + ty + j) * Dfeat + d0 + tx] = t[tx][ty + j];
}

// ---------------- 3-NN + weights: 2 points / thread ----------------
__global__ void knn_kernel(const float* __restrict__ xyz1, const float* __restrict__ xyz2) {
    __shared__ float4 sP[Spts];   // {-2x, -2y, -2z, |x|^2}
    int b = blockIdx.y;
    int nA = blockIdx.x * 256 + threadIdx.x;
    int nB = nA + 128;
    const float* x2 = xyz2 + (size_t)b * 3 * Spts;
    for (int s = threadIdx.x; s < Spts; s += 128) {
        float X = x2[s], Y = x2[Spts + s], Z = x2[2 * Spts + s];
        sP[s] = make_float4(-2.f * X, -2.f * Y, -2.f * Z, X * X + Y * Y + Z * Z);
    }
    __syncthreads();
    const float* x1 = xyz1 + (size_t)b * 3 * Npts;
    float ax = x1[nA], ay = x1[Npts + nA], az = x1[2 * Npts + nA];
    float bx = x1[nB], by = x1[Npts + nB], bz = x1[2 * Npts + nB];
    float na = ax * ax + ay * ay + az * az;
    float nb = bx * bx + by * by + bz * bz;
    float a0 = 3.4e38f, a1 = 3.4e38f, a2 = 3.4e38f;
    float b0 = 3.4e38f, b1 = 3.4e38f, b2 = 3.4e38f;
    int ia0 = 0, ia1 = 0, ia2 = 0, ib0 = 0, ib1 = 0, ib2 = 0;
#pragma unroll 4
    for (int s = 0; s < Spts; s++) {
        float4 q = sP[s];
        float da = fmaf(q.x, ax, fmaf(q.y, ay, fmaf(q.z, az, q.w)));
        float db = fmaf(q.x, bx, fmaf(q.y, by, fmaf(q.z, bz, q.w)));
        if (da < a2) {
            if (da < a1) {
                a2 = a1; ia2 = ia1;
                if (da < a0) { a1 = a0; ia1 = ia0; a0 = da; ia0 = s; }
                else         { a1 = da; ia1 = s; }
            } else { a2 = da; ia2 = s; }
        }
        if (db < b2) {
            if (db < b1) {
                b2 = b1; ib2 = ib1;
                if (db < b0) { b1 = b0; ib1 = ib0; b0 = db; ib0 = s; }
                else         { b1 = db; ib1 = s; }
            } else { b2 = db; ib2 = s; }
        }
    }
    {
        float r0 = 1.0f / (a0 + na + 1e-8f);
        float r1 = 1.0f / (a1 + na + 1e-8f);
        float r2 = 1.0f / (a2 + na + 1e-8f);
        float rs = 1.0f / (r0 + r1 + r2);
        int o = (b * Npts + nA) * 3;
        g_w3[o] = r0 * rs; g_w3[o + 1] = r1 * rs; g_w3[o + 2] = r2 * rs;
        g_i3[o] = ia0;     g_i3[o + 1] = ia1;     g_i3[o + 2] = ia2;
    }
    {
        float r0 = 1.0f / (b0 + nb + 1e-8f);
        float r1 = 1.0f / (b1 + nb + 1e-8f);
        float r2 = 1.0f / (b2 + nb + 1e-8f);
        float rs = 1.0f / (r0 + r1 + r2);
        int o = (b * Npts + nB) * 3;
        g_w3[o] = r0 * rs; g_w3[o + 1] = r1 * rs; g_w3[o + 2] = r2 * rs;
        g_i3[o] = ib0;     g_i3[o + 1] = ib1;     g_i3[o + 2] = ib2;
    }
}

// ---------------- interpolation -> g_xh rows 256..511 (fp16) ----------------
__global__ void interp_kernel() {
    __shared__ float tile[256 * 33];
    int b   = blockIdx.y;
    int n0  = blockIdx.x * 32;
    int tid = threadIdx.x, lane = tid & 31, wid = tid >> 5;
#pragma unroll
    for (int p = 0; p < 4; p++) {
        int nloc = wid * 4 + p;
        int n    = n0 + nloc;
        int base = (b * Npts + n) * 3;
        float w0 = g_w3[base], w1 = g_w3[base + 1], w2 = g_w3[base + 2];
        const float* r0 = g_p2t + ((size_t)b * Spts + g_i3[base])     * Dfeat;
        const float* r1 = g_p2t + ((size_t)b * Spts + g_i3[base + 1]) * Dfeat;
        const float* r2 = g_p2t + ((size_t)b * Spts + g_i3[base + 2]) * Dfeat;
#pragma unroll
        for (int j = 0; j < 8; j++) {
            int d = lane + 32 * j;
            tile[d * 33 + nloc] = w0 * r0[d] + w1 * r1[d] + w2 * r2[d];
        }
    }
    __syncthreads();
    __half* outb = g_xh + ((size_t)b * CIN + Dfeat) * Npts;
#pragma unroll 4
    for (int e = tid; e < 256 * 32; e += 256) {
        int d = e >> 5, nl = e & 31;
        outb[(size_t)d * Npts + n0 + nl] = __float2half_rn(tile[d * 33 + nl]);
    }
}

// ---------------- points1 fp32 -> g_xh rows 0..255 (fp16) ----------------
__global__ void p1h_kernel(const float* __restrict__ p1) {
    size_t i = (size_t)blockIdx.x * 256 + threadIdx.x;     // 8-float unit
    size_t f = i * 8;
    int b = (int)(f / ((size_t)Dfeat * Npts));
    size_t rem = f - (size_t)b * Dfeat * Npts;
    float4 v0 = *(const float4*)(p1 + f);
    float4 v1 = *(const float4*)(p1 + f + 4);
    __half2 h0 = __floats2half2_rn(v0.x, v0.y);
    __half2 h1 = __floats2half2_rn(v0.z, v0.w);
    __half2 h2 = __floats2half2_rn(v1.x, v1.y);
    __half2 h3 = __floats2half2_rn(v1.z, v1.w);
    uint4 pk = make_uint4(*(uint32_t*)&h0, *(uint32_t*)&h1, *(uint32_t*)&h2, *(uint32_t*)&h3);
    *(uint4*)(g_xh + (size_t)b * CIN * Npts + rem) = pk;
}

// ---------------- weight split fp32 -> fp16 hi/lo ----------------
__global__ void split_w_kernel(const float* __restrict__ src, int which, int n) {
    int i = blockIdx.x * 256 + threadIdx.x;
    if (i >= n) return;
    float v = src[i];
    __half h = __float2half_rn(v);
    __half l = __float2half_rn(v - __half2float(h));
    if (which) { g_w1h[i] = h; g_w1l[i] = l; }
    else       { g_w0h[i] = h; g_w0l[i] = l; }
}

// ---------------- stats zero / finalize ----------------
__global__ void zero_stats_kernel() {
    int t = threadIdx.x;
    g_sum0[t] = 0.f; g_sq0[t] = 0.f; g_sum1[t] = 0.f; g_sq1[t] = 0.f;
}
__global__ void finalize0_kernel(const float* __restrict__ g, const float* __restrict__ be) {
    int c = threadIdx.x;
    float mean = g_sum0[c] * CNT_INV;
    float var  = g_sq0[c] * CNT_INV - mean * mean;
    float a    = g[c] * rsqrtf(var + 1e-5f);
    g_a0[c] = a; g_be0[c] = be[c] - mean * a;
}
__global__ void finalize1_kernel(const float* __restrict__ g, const float* __restrict__ be) {
    int c = threadIdx.x;
    float mean = g_sum1[c] * CNT_INV;
    float var  = g_sq1[c] * CNT_INV - mean * mean;
    float a    = g[c] * rsqrtf(var + 1e-5f);
    g_a1[c] = a; g_be1[c] = be[c] - mean * a;
}

// ---------------- in-place BN1 + ReLU on g_y0h ----------------
__global__ void bn1_kernel() {
    size_t i = (size_t)blockIdx.x * 256 + threadIdx.x;     // uint4 (8 halfs)
    int c = (int)((i >> 11) & 255);                        // Npts/8 = 2048 uint4 per row
    float a = g_a0[c], be = g_be0[c];
    uint4 raw = ((uint4*)g_y0h)[i];
    __half2* hp = (__half2*)&raw;
#pragma unroll
    for (int j = 0; j < 4; j++) {
        float2 f = __half22float2(hp[j]);
        f.x = fmaxf(fmaf(a, f.x, be), 0.f);
        f.y = fmaxf(fmaf(a, f.y, be), 0.f);
        hp[j] = __floats2half2_rn(f.x, f.y);
    }
    ((uint4*)g_y0h)[i] = raw;
}

// ---------------- fp16 2-term HMMA GEMM, M=256 per CTA, cp.async pipelined ----------------
// out[256, 16384] = (Wh+Wl) @ X per batch. CTA: full 256 M x 128 N, K-chunk 32, 512 thr.
// smem: A (hi+lo, swizzled, single-buffered) 32KB + B (2-stage, swizzled) 16KB = 48KB.
__global__ __launch_bounds__(512, 1)
void gemm_mma_kernel(int which, float* __restrict__ outp) {
    __shared__ __half sA[2][8192];    // [split][256 rows x 32 k], chunk^((r>>1)&3) swizzle
    __shared__ __half sB[2][4096];    // [stage][32 k x 128 n],   chunk^(r&7) swizzle

    const int K  = which ? CMID : CIN;
    const int nc = K / 32;
    const int tid = threadIdx.x;
    const int lane = tid & 31, warp = tid >> 5;
    const int b  = blockIdx.y;
    const int n0 = blockIdx.x * 128;
    const int wm = (warp >> 1) * 32;
    const int wn = (warp & 1) * 64;

    const __half* Wh = which ? g_w1h : g_w0h;
    const __half* Wl = which ? g_w1l : g_w0l;
    const __half* Bg = (which ? g_y0h : g_xh) + (size_t)b * K * Npts + n0;
    float* sum = which ? g_sum1 : g_sum0;
    float* sq  = which ? g_sq1  : g_sq0;

    const uint32_t uA = smem_u32(sA), uB = smem_u32(sB);

    // B staging: thread -> (row k = tid>>4, 16B chunk = tid&15)
    const int brr = tid >> 4, bcc = tid & 15;
    const __half* bgp = Bg + (size_t)brr * Npts + bcc * 8;
    const uint32_t bso = (uint32_t)(brr * 256 + ((bcc ^ (brr & 7)) * 16));

    float acc[2][8][4];
#pragma unroll
    for (int t = 0; t < 2; t++)
#pragma unroll
        for (int j = 0; j < 8; j++)
#pragma unroll
            for (int q = 0; q < 4; q++) acc[t][j][q] = 0.f;

    cp16(uB + bso, bgp);                    // B chunk 0 -> stage 0
    CP_COMMIT();

    for (int c = 0; c < nc; c++) {
        // A(c): 2048 x 16B, 4 per thread (hi+lo)
#pragma unroll
        for (int j = 0; j < 4; j++) {
            int idx = j * 512 + tid;
            int split = idx >> 10, rem = idx & 1023;
            int r = rem >> 2, cc = rem & 3;
            const __half* gw = (split ? Wl : Wh) + (size_t)r * K + c * 32 + cc * 8;
            cp16(uA + split * 16384 + (uint32_t)(r * 64 + ((cc ^ ((r >> 1) & 3)) * 16)), gw);
        }
        CP_COMMIT();
        if (c + 1 < nc) {
            cp16(uB + ((c + 1) & 1) * 8192 + bso, bgp + (size_t)(c + 1) * 32 * Npts);
            CP_COMMIT();
            asm volatile("cp.async.wait_group 1;" ::: "memory");
        } else {
            asm volatile("cp.async.wait_group 0;" ::: "memory");
        }
        __syncthreads();

        const uint32_t uBs = uB + (c & 1) * 8192;
#pragma unroll
        for (int ks = 0; ks < 2; ks++) {
            uint32_t ah[2][4], al[2][4];
#pragma unroll
            for (int t = 0; t < 2; t++) {
                int r = wm + (lane & 15) + t * 16;
                int cc = ks * 2 + (lane >> 4);
                uint32_t adr = uA + (uint32_t)(r * 64 + ((cc ^ ((r >> 1) & 3)) * 16));
                LDSM4(ah[t], adr);
                LDSM4(al[t], adr + 16384);
            }
#pragma unroll
            for (int jn = 0; jn < 4; jn++) {
                int r = ks * 16 + (lane & 15);
                int cc = wn / 8 + (lane >> 4) + jn * 2;
                uint32_t bh[4];
                LDSM4T(bh, uBs + (uint32_t)(r * 256 + ((cc ^ (r & 7)) * 16)));
                MMA16816(acc[0][jn * 2],     ah[0], bh[0], bh[1]);
                MMA16816(acc[1][jn * 2],     ah[1], bh[0], bh[1]);
                MMA16816(acc[0][jn * 2 + 1], ah[0], bh[2], bh[3]);
                MMA16816(acc[1][jn * 2 + 1], ah[1], bh[2], bh[3]);
                MMA16816(acc[0][jn * 2],     al[0], bh[0], bh[1]);
                MMA16816(acc[1][jn * 2],     al[1], bh[0], bh[1]);
                MMA16816(acc[0][jn * 2 + 1], al[0], bh[2], bh[3]);
                MMA16816(acc[1][jn * 2 + 1], al[1], bh[2], bh[3]);
            }
        }
        __syncthreads();
    }

    // ---- epilogue: store (fp16 y0 | fp32 out) + fused per-channel stats ----
    const int gr = lane >> 2, qc = (lane & 3) * 2;
#pragma unroll
    for (int t = 0; t < 2; t++) {
        int ch0 = wm + t * 16 + gr;              // rows ch0 and ch0+8 (M=256 full)
        float s0 = 0.f, q0 = 0.f, s1 = 0.f, q1 = 0.f;
        size_t col = (size_t)n0 + wn + qc;
#pragma unroll
        for (int j = 0; j < 8; j++) {
            float2 v = {acc[t][j][0], acc[t][j][1]};
            float2 w = {acc[t][j][2], acc[t][j][3]};
            s0 += v.x + v.y; q0 += v.x * v.x + v.y * v.y;
            s1 += w.x + w.y; q1 += w.x * w.x + w.y * w.y;
            if (which) {
                float* p0 = outp + ((size_t)b * 256 + ch0) * Npts + col + j * 8;
                *(float2*)p0 = v;
                *(float2*)(p0 + 8 * (size_t)Npts) = w;
            } else {
                __half* p0 = g_y0h + ((size_t)b * 256 + ch0) * Npts + col + j * 8;
                *(__half2*)p0 = __floats2half2_rn(v.x, v.y);
                *(__half2*)(p0 + 8 * (size_t)Npts) = __floats2half2_rn(w.x, w.y);
            }
        }
#pragma unroll
        for (int o = 1; o < 4; o <<= 1) {
            s0 += __shfl_xor_sync(0xffffffffu, s0, o);
            q0 += __shfl_xor_sync(0xffffffffu, q0, o);
            s1 += __shfl_xor_sync(0xffffffffu, s1, o);
            q1 += __shfl_xor_sync(0xffffffffu, q1, o);
        }
        if ((lane & 3) == 0) {
            atomicAdd(sum + ch0, s0);      atomicAdd(sq + ch0, q0);
            atomicAdd(sum + ch0 + 8, s1);  atomicAdd(sq + ch0 + 8, q1);
        }
    }
}

// ---------------- final BN2 + ReLU in place on d_out ----------------
__global__ void bnrelu_kernel(float* __restrict__ out) {
    size_t i = (size_t)blockIdx.x * 256 + threadIdx.x;   // float4 index
    int c = (int)((i / (Npts / 4)) & (COUT - 1));
    float a = g_a1[c], be = g_be1[c];
    float4 v = ((float4*)out)[i];
    v.x = fmaxf(fmaf(a, v.x, be), 0.f);
    v.y = fmaxf(fmaf(a, v.y, be), 0.f);
    v.z = fmaxf(fmaf(a, v.z, be), 0.f);
    v.w = fmaxf(fmaf(a, v.w, be), 0.f);
    ((float4*)out)[i] = v;
}

// ---------------- launch ----------------
extern "C" void kernel_launch(void* const* d_in, const int* in_sizes, int n_in,
                              void* d_out, int out_size) {
    const float* xyz1    = (const float*)d_in[0];
    const float* xyz2    = (const float*)d_in[1];
    const float* points1 = (const float*)d_in[2];
    const float* points2 = (const float*)d_in[3];
    const float* w0      = (const float*)d_in[4];
    const float* g0      = (const float*)d_in[6];
    const float* be0     = (const float*)d_in[7];
    const float* w1      = (const float*)d_in[8];
    const float* g1      = (const float*)d_in[10];
    const float* be1     = (const float*)d_in[11];
    float* out = (float*)d_out;

    split_w_kernel<<<(CMID * CIN + 255) / 256, 256>>>(w0, 0, CMID * CIN);
    split_w_kernel<<<(COUT * CMID + 255) / 256, 256>>>(w1, 1, COUT * CMID);
    transpose_p2_kernel<<<dim3(Spts / 32, Dfeat / 32, Bsz), dim3(32, 8)>>>(points2);
    knn_kernel<<<dim3(Npts / 256, Bsz), 128>>>(xyz1, xyz2);
    p1h_kernel<<<(int)(((size_t)Bsz * Dfeat * Npts / 8) / 256), 256>>>(points1);
    interp_kernel<<<dim3(Npts / 32, Bsz), 256>>>();
    zero_stats_kernel<<<1, 256>>>();
    gemm_mma_kernel<<<dim3(Npts / 128, Bsz), 512>>>(0, out);
    finalize0_kernel<<<1, CMID>>>(g0, be0);
    bn1_kernel<<<(int)(((size_t)Bsz * CMID * Npts / 8) / 256), 256>>>();
    gemm_mma_kernel<<<dim3(Npts / 128, Bsz), 512>>>(1, out);
    finalize1_kernel<<<1, COUT>>>(g1, be1);
    bnrelu_kernel<<<(int)(((size_t)Bsz * COUT * Npts / 4) / 256), 256>>>(out);
}

// round 13
// speedup vs baseline: 1.0326x; 1.0326x over previous
#include <cuda_runtime.h>
#include <cuda_fp16.h>
#include <cstdint>

#define Bsz   8
#define Npts  16384
#define Spts  1024
#define Dfeat 256
#define CIN   512
#define CMID  256
#define COUT  256
#define CNT_INV (1.0f / (8.0f * 16384.0f))

// ---------------- scratch (device globals; no runtime allocation) ----------------
__device__ __align__(128) float g_p2t[Bsz * Spts * Dfeat];            // points2^T [B,S,D]
__device__ float g_w3[Bsz * Npts * 3];
__device__ int   g_i3[Bsz * Npts * 3];
__device__ __align__(128) __half g_ih[(size_t)Bsz * Dfeat * Npts];    // interp [B,256,N] fp16
__device__ __align__(128) __half g_y0h[(size_t)Bsz * CMID * Npts];    // y0 [B,256,N] fp16
__device__ __align__(128) __half g_w0h[CMID * CIN], g_w0l[CMID * CIN];
__device__ __align__(128) __half g_w1h[COUT * CMID], g_w1l[COUT * CMID];
__device__ float g_sum0[CMID], g_sq0[CMID], g_sum1[COUT], g_sq1[COUT];
__device__ float g_a0[CMID], g_be0[CMID], g_a1[COUT], g_be1[COUT];

// ---------------- helpers ----------------
__device__ __forceinline__ uint32_t smem_u32(const void* p) {
    uint32_t a;
    asm("{ .reg .u64 t; cvta.to.shared.u64 t, %1; cvt.u32.u64 %0, t; }" : "=r"(a) : "l"(p));
    return a;
}
__device__ __forceinline__ void cp16(uint32_t dst, const void* src) {
    asm volatile("cp.async.cg.shared.global [%0], [%1], 16;" :: "r"(dst), "l"(src));
}
#define CP_COMMIT() asm volatile("cp.async.commit_group;" ::: "memory")
#define LDSM4(R, A) \
    asm volatile("ldmatrix.sync.aligned.m8n8.x4.shared.b16 {%0,%1,%2,%3}, [%4];" \
        : "=r"((R)[0]), "=r"((R)[1]), "=r"((R)[2]), "=r"((R)[3]) : "r"(A))
#define LDSM4T(R, A) \
    asm volatile("ldmatrix.sync.aligned.m8n8.x4.trans.shared.b16 {%0,%1,%2,%3}, [%4];" \
        : "=r"((R)[0]), "=r"((R)[1]), "=r"((R)[2]), "=r"((R)[3]) : "r"(A))
#define MMA16816(C, A, B0, B1) \
    asm volatile("mma.sync.aligned.m16n8k16.row.col.f32.f16.f16.f32 " \
        "{%0,%1,%2,%3}, {%4,%5,%6,%7}, {%8,%9}, {%0,%1,%2,%3};" \
        : "+f"((C)[0]), "+f"((C)[1]), "+f"((C)[2]), "+f"((C)[3]) \
        : "r"((A)[0]), "r"((A)[1]), "r"((A)[2]), "r"((A)[3]), "r"(B0), "r"(B1))

// ---------------- transpose points2 [B,D,S] -> [B,S,D] ----------------
__global__ void transpose_p2_kernel(const float* __restrict__ p2) {
    __shared__ float t[32][33];
    int b = blockIdx.z, s0 = blockIdx.x * 32, d0 = blockIdx.y * 32;
    int tx = threadIdx.x, ty = threadIdx.y;
    const float* src = p2 + (size_t)b * Dfeat * Spts;
#pragma unroll
    for (int j = 0; j < 32; j += 8)
        t[ty + j][tx] = src[(size_t)(d0 + ty + j) * Spts + s0 + tx];
    __syncthreads();
    float* dst = g_p2t + (size_t)b * Spts * Dfeat;
#pragma unroll
    for (int j = 0; j < 32; j += 8)
        dst[(size_t)(s0 + ty + j) * Dfeat + d0 + tx] = t[tx][ty + j];
}

// ---------------- 3-NN + inverse-distance weights (R11 version) ----------------
__global__ void knn_kernel(const float* __restrict__ xyz1, const float* __restrict__ xyz2) {
    __shared__ float4 sP[Spts];    // {-2x, -2y, -2z, |x|^2}
    int b = blockIdx.y;
    int n = blockIdx.x * blockDim.x + threadIdx.x;
    const float* x2 = xyz2 + (size_t)b * 3 * Spts;
    for (int s = threadIdx.x; s < Spts; s += blockDim.x) {
        float X = x2[s], Y = x2[Spts + s], Z = x2[2 * Spts + s];
        sP[s] = make_float4(-2.f * X, -2.f * Y, -2.f * Z, X * X + Y * Y + Z * Z);
    }
    __syncthreads();
    const float* x1 = xyz1 + (size_t)b * 3 * Npts;
    float px = x1[n], py = x1[Npts + n], pz = x1[2 * Npts + n];
    float n1 = px * px + py * py + pz * pz;
    float d0 = 3.4e38f, d1 = 3.4e38f, d2 = 3.4e38f;
    int   i0 = 0, i1 = 0, i2 = 0;
#pragma unroll 8
    for (int s = 0; s < Spts; s++) {
        float4 q = sP[s];
        float d = fmaf(q.x, px, fmaf(q.y, py, fmaf(q.z, pz, q.w)));
        if (d < d2) {
            if (d < d1) {
                d2 = d1; i2 = i1;
                if (d < d0) { d1 = d0; i1 = i0; d0 = d; i0 = s; }
                else        { d1 = d;  i1 = s; }
            } else { d2 = d; i2 = s; }
        }
    }
    float r0 = 1.0f / (d0 + n1 + 1e-8f);
    float r1 = 1.0f / (d1 + n1 + 1e-8f);
    float r2 = 1.0f / (d2 + n1 + 1e-8f);
    float rs = 1.0f / (r0 + r1 + r2);
    int o = (b * Npts + n) * 3;
    g_w3[o] = r0 * rs; g_w3[o + 1] = r1 * rs; g_w3[o + 2] = r2 * rs;
    g_i3[o] = i0;      g_i3[o + 1] = i1;      g_i3[o + 2] = i2;
}

// ---------------- interpolation -> g_ih [B,256,N] fp16 ----------------
__global__ void interp_kernel() {
    __shared__ float tile[256 * 33];
    int b   = blockIdx.y;
    int n0  = blockIdx.x * 32;
    int tid = threadIdx.x, lane = tid & 31, wid = tid >> 5;
#pragma unroll
    for (int p = 0; p < 4; p++) {
        int nloc = wid * 4 + p;
        int n    = n0 + nloc;
        int base = (b * Npts + n) * 3;
        float w0 = g_w3[base], w1 = g_w3[base + 1], w2 = g_w3[base + 2];
        const float* r0 = g_p2t + ((size_t)b * Spts + g_i3[base])     * Dfeat;
        const float* r1 = g_p2t + ((size_t)b * Spts + g_i3[base + 1]) * Dfeat;
        const float* r2 = g_p2t + ((size_t)b * Spts + g_i3[base + 2]) * Dfeat;
#pragma unroll
        for (int j = 0; j < 8; j++) {
            int d = lane + 32 * j;
            tile[d * 33 + nloc] = w0 * r0[d] + w1 * r1[d] + w2 * r2[d];
        }
    }
    __syncthreads();
    __half* outb = g_ih + (size_t)b * Dfeat * Npts;
#pragma unroll 4
    for (int e = tid; e < 256 * 32; e += 256) {
        int d = e >> 5, nl = e & 31;
        outb[(size_t)d * Npts + n0 + nl] = __float2half_rn(tile[d * 33 + nl]);
    }
}

// ---------------- weight split fp32 -> fp16 hi/lo ----------------
__global__ void split_w_kernel(const float* __restrict__ src, int which, int n) {
    int i = blockIdx.x * 256 + threadIdx.x;
    if (i >= n) return;
    float v = src[i];
    __half h = __float2half_rn(v);
    __half l = __float2half_rn(v - __half2float(h));
    if (which) { g_w1h[i] = h; g_w1l[i] = l; }
    else       { g_w0h[i] = h; g_w0l[i] = l; }
}

// ---------------- stats zero / finalize ----------------
__global__ void zero_stats_kernel() {
    int t = threadIdx.x;
    g_sum0[t] = 0.f; g_sq0[t] = 0.f; g_sum1[t] = 0.f; g_sq1[t] = 0.f;
}
__global__ void finalize0_kernel(const float* __restrict__ g, const float* __restrict__ be) {
    int c = threadIdx.x;
    float mean = g_sum0[c] * CNT_INV;
    float var  = g_sq0[c] * CNT_INV - mean * mean;
    float a    = g[c] * rsqrtf(var + 1e-5f);
    g_a0[c] = a; g_be0[c] = be[c] - mean * a;
}
__global__ void finalize1_kernel(const float* __restrict__ g, const float* __restrict__ be) {
    int c = threadIdx.x;
    float mean = g_sum1[c] * CNT_INV;
    float var  = g_sq1[c] * CNT_INV - mean * mean;
    float a    = g[c] * rsqrtf(var + 1e-5f);
    g_a1[c] = a; g_be1[c] = be[c] - mean * a;
}

// ---------------- fp16 2-term HMMA GEMM, M=256/CTA, reg-prefetched B, fused transforms ----
// out[256, 16384] = (Wh+Wl) @ X per batch. 512 thr, K-chunk 32, B double-buffered in smem.
// which=0: B rows 0..255 = fp32 points1 (convert in staging), 256..511 = g_ih fp16;
//          dst = g_y0h fp16, stats0.
// which=1: B = bn1+relu(g_y0h) applied in staging; dst = out fp32, stats1.
__global__ __launch_bounds__(512, 1)
void gemm_mma_kernel(int which, const float* __restrict__ p1, float* __restrict__ outp) {
    __shared__ __half sA[2][8192];    // [split][256 rows x 32 k], swizzle cc^((r>>1)&3)
    __shared__ __half sB[2][4096];    // [stage][32 k x 128 n],   swizzle cc^(r&7)

    const int K  = which ? CMID : CIN;
    const int nc = K / 32;
    const int tid = threadIdx.x;
    const int lane = tid & 31, warp = tid >> 5;
    const int b  = blockIdx.y;
    const int n0 = blockIdx.x * 128;
    const int wm = (warp >> 1) * 32;
    const int wn = (warp & 1) * 64;

    const __half* Wh = which ? g_w1h : g_w0h;
    const __half* Wl = which ? g_w1l : g_w0l;
    float* sum = which ? g_sum1 : g_sum0;
    float* sq  = which ? g_sq1  : g_sq0;

    const uint32_t uA = smem_u32(sA), uB = smem_u32(sB);

    // B staging geometry: row k = brr, 8-half chunk = bcc
    const int brr = tid >> 4, bcc = tid & 15;
    const uint32_t bso = (uint32_t)(brr * 256 + ((bcc ^ (brr & 7)) * 16));

    // ---- B chunk fetch (regular loads + transform) ----
    auto load_b = [&](int c) -> uint4 {
        int k = c * 32 + brr;
        size_t coloff = (size_t)n0 + bcc * 8;
        if (which) {
            uint4 raw = *(const uint4*)(g_y0h + ((size_t)b * CMID + k) * Npts + coloff);
            float a = g_a0[k], be = g_be0[k];
            __half2* hp = (__half2*)&raw;
#pragma unroll
            for (int j = 0; j < 4; j++) {
                float2 f = __half22float2(hp[j]);
                f.x = fmaxf(fmaf(a, f.x, be), 0.f);
                f.y = fmaxf(fmaf(a, f.y, be), 0.f);
                hp[j] = __floats2half2_rn(f.x, f.y);
            }
            return raw;
        } else if (k < Dfeat) {
            const float* src = p1 + ((size_t)b * Dfeat + k) * Npts + coloff;
            float4 v0 = *(const float4*)src;
            float4 v1 = *(const float4*)(src + 4);
            __half2 h0 = __floats2half2_rn(v0.x, v0.y);
            __half2 h1 = __floats2half2_rn(v0.z, v0.w);
            __half2 h2 = __floats2half2_rn(v1.x, v1.y);
            __half2 h3 = __floats2half2_rn(v1.z, v1.w);
            return make_uint4(*(uint32_t*)&h0, *(uint32_t*)&h1,
                              *(uint32_t*)&h2, *(uint32_t*)&h3);
        } else {
            return *(const uint4*)(g_ih + ((size_t)b * Dfeat + (k - Dfeat)) * Npts + coloff);
        }
    };

    float acc[2][8][4];
#pragma unroll
    for (int t = 0; t < 2; t++)
#pragma unroll
        for (int j = 0; j < 8; j++)
#pragma unroll
            for (int q = 0; q < 4; q++) acc[t][j][q] = 0.f;

    uint4 breg = load_b(0);

    for (int c = 0; c < nc; c++) {
        // A(c): 2048 x 16B cp.async, 4 per thread (hi+lo). Safe: end-of-iter sync
        // guarantees MMA(c-1) finished reading sA before these stores can land.
#pragma unroll
        for (int j = 0; j < 4; j++) {
            int idx = j * 512 + tid;
            int split = idx >> 10, rem = idx & 1023;
            int r = rem >> 2, cc = rem & 3;
            const __half* gw = (split ? Wl : Wh) + (size_t)r * K + c * 32 + cc * 8;
            cp16(uA + split * 16384 + (uint32_t)(r * 64 + ((cc ^ ((r >> 1) & 3)) * 16)), gw);
        }
        CP_COMMIT();
        // store staged B(c); prefetch B(c+1) (hidden behind MMA of chunk c)
        *(uint4*)((char*)sB + (c & 1) * 8192 + bso) = breg;
        if (c + 1 < nc) breg = load_b(c + 1);
        asm volatile("cp.async.wait_group 0;" ::: "memory");
        __syncthreads();

        const uint32_t uBs = uB + (c & 1) * 8192;
#pragma unroll
        for (int ks = 0; ks < 2; ks++) {
            uint32_t ah[2][4], al[2][4];
#pragma unroll
            for (int t = 0; t < 2; t++) {
                int r = wm + (lane & 15) + t * 16;
                int cc = ks * 2 + (lane >> 4);
                uint32_t adr = uA + (uint32_t)(r * 64 + ((cc ^ ((r >> 1) & 3)) * 16));
                LDSM4(ah[t], adr);
                LDSM4(al[t], adr + 16384);
            }
#pragma unroll
            for (int jn = 0; jn < 4; jn++) {
                int r = ks * 16 + (lane & 15);
                int cc = wn / 8 + (lane >> 4) + jn * 2;
                uint32_t bh[4];
                LDSM4T(bh, uBs + (uint32_t)(r * 256 + ((cc ^ (r & 7)) * 16)));
                MMA16816(acc[0][jn * 2],     ah[0], bh[0], bh[1]);
                MMA16816(acc[1][jn * 2],     ah[1], bh[0], bh[1]);
                MMA16816(acc[0][jn * 2 + 1], ah[0], bh[2], bh[3]);
                MMA16816(acc[1][jn * 2 + 1], ah[1], bh[2], bh[3]);
                MMA16816(acc[0][jn * 2],     al[0], bh[0], bh[1]);
                MMA16816(acc[1][jn * 2],     al[1], bh[0], bh[1]);
                MMA16816(acc[0][jn * 2 + 1], al[0], bh[2], bh[3]);
                MMA16816(acc[1][jn * 2 + 1], al[1], bh[2], bh[3]);
            }
        }
        __syncthreads();
    }

    // ---- epilogue: store (fp16 y0 | fp32 out) + fused per-channel stats ----
    const int gr = lane >> 2, qc = (lane & 3) * 2;
#pragma unroll
    for (int t = 0; t < 2; t++) {
        int ch0 = wm + t * 16 + gr;              // rows ch0 and ch0+8 (M=256 full)
        float s0 = 0.f, q0 = 0.f, s1 = 0.f, q1 = 0.f;
        size_t col = (size_t)n0 + wn + qc;
#pragma unroll
        for (int j = 0; j < 8; j++) {
            float2 v = {acc[t][j][0], acc[t][j][1]};
            float2 w = {acc[t][j][2], acc[t][j][3]};
            s0 += v.x + v.y; q0 += v.x * v.x + v.y * v.y;
            s1 += w.x + w.y; q1 += w.x * w.x + w.y * w.y;
            if (which) {
                float* p0 = outp + ((size_t)b * 256 + ch0) * Npts + col + j * 8;
                *(float2*)p0 = v;
                *(float2*)(p0 + 8 * (size_t)Npts) = w;
            } else {
                __half* p0 = g_y0h + ((size_t)b * 256 + ch0) * Npts + col + j * 8;
                *(__half2*)p0 = __floats2half2_rn(v.x, v.y);
                *(__half2*)(p0 + 8 * (size_t)Npts) = __floats2half2_rn(w.x, w.y);
            }
        }
#pragma unroll
        for (int o = 1; o < 4; o <<= 1) {
            s0 += __shfl_xor_sync(0xffffffffu, s0, o);
            q0 += __shfl_xor_sync(0xffffffffu, q0, o);
            s1 += __shfl_xor_sync(0xffffffffu, s1, o);
            q1 += __shfl_xor_sync(0xffffffffu, q1, o);
        }
        if ((lane & 3) == 0) {
            atomicAdd(sum + ch0, s0);      atomicAdd(sq + ch0, q0);
            atomicAdd(sum + ch0 + 8, s1);  atomicAdd(sq + ch0 + 8, q1);
        }
    }
}

// ---------------- final BN2 + ReLU in place on d_out ----------------
__global__ void bnrelu_kernel(float* __restrict__ out) {
    size_t i = (size_t)blockIdx.x * 256 + threadIdx.x;   // float4 index
    int c = (int)((i / (Npts / 4)) & (COUT - 1));
    float a = g_a1[c], be = g_be1[c];
    float4 v = ((float4*)out)[i];
    v.x = fmaxf(fmaf(a, v.x, be), 0.f);
    v.y = fmaxf(fmaf(a, v.y, be), 0.f);
    v.z = fmaxf(fmaf(a, v.z, be), 0.f);
    v.w = fmaxf(fmaf(a, v.w, be), 0.f);
    ((float4*)out)[i] = v;
}

// ---------------- launch ----------------
extern "C" void kernel_launch(void* const* d_in, const int* in_sizes, int n_in,
                              void* d_out, int out_size) {
    const float* xyz1    = (const float*)d_in[0];
    const float* xyz2    = (const float*)d_in[1];
    const float* points1 = (const float*)d_in[2];
    const float* points2 = (const float*)d_in[3];
    const float* w0      = (const float*)d_in[4];
    const float* g0      = (const float*)d_in[6];
    const float* be0     = (const float*)d_in[7];
    const float* w1      = (const float*)d_in[8];
    const float* g1      = (const float*)d_in[10];
    const float* be1     = (const float*)d_in[11];
    float* out = (float*)d_out;

    split_w_kernel<<<(CMID * CIN + 255) / 256, 256>>>(w0, 0, CMID * CIN);
    split_w_kernel<<<(COUT * CMID + 255) / 256, 256>>>(w1, 1, COUT * CMID);
    transpose_p2_kernel<<<dim3(Spts / 32, Dfeat / 32, Bsz), dim3(32, 8)>>>(points2);
    knn_kernel<<<dim3(Npts / 256, Bsz), 256>>>(xyz1, xyz2);
    interp_kernel<<<dim3(Npts / 32, Bsz), 256>>>();
    zero_stats_kernel<<<1, 256>>>();
    gemm_mma_kernel<<<dim3(Npts / 128, Bsz), 512>>>(0, points1, out);
    finalize0_kernel<<<1, CMID>>>(g0, be0);
    gemm_mma_kernel<<<dim3(Npts / 128, Bsz), 512>>>(1, points1, out);
    finalize1_kernel<<<1, COUT>>>(g1, be1);
    bnrelu_kernel<<<(int)(((size_t)Bsz * COUT * Npts / 4) / 256), 256>>>(out);
}

// round 14
// speedup vs baseline: 1.1310x; 1.0953x over previous
#include <cuda_runtime.h>
#include <cuda_fp16.h>
#include <cstdint>

#define Bsz   8
#define Npts  16384
#define Spts  1024
#define Dfeat 256
#define CIN   512
#define CMID  256
#define COUT  256
#define CNT_INV (1.0f / (8.0f * 16384.0f))

// ---------------- scratch (device globals; no runtime allocation) ----------------
__device__ __align__(128) float g_p2t[Bsz * Spts * Dfeat];            // points2^T [B,S,D]
__device__ float g_w3[Bsz * Npts * 3];
__device__ int   g_i3[Bsz * Npts * 3];
__device__ __align__(128) __half g_ih[(size_t)Bsz * Dfeat * Npts];    // interp [B,D,N] fp16
__device__ __align__(128) __half g_y0h[(size_t)Bsz * CMID * Npts];    // raw GEMM1 out fp16
__device__ __align__(128) __half g_w0h[CMID * CIN], g_w0l[CMID * CIN];
__device__ __align__(128) __half g_w1h[COUT * CMID], g_w1l[COUT * CMID];
__device__ float g_sum0[CMID], g_sq0[CMID], g_sum1[COUT], g_sq1[COUT];
__device__ float g_a0[CMID], g_be0[CMID], g_a1[COUT], g_be1[COUT];

// ---------------- helpers ----------------
__device__ __forceinline__ uint32_t smem_u32(const void* p) {
    uint32_t a;
    asm("{ .reg .u64 t; cvta.to.shared.u64 t, %1; cvt.u32.u64 %0, t; }" : "=r"(a) : "l"(p));
    return a;
}
#define LDSM4(R, A) \
    asm volatile("ldmatrix.sync.aligned.m8n8.x4.shared.b16 {%0,%1,%2,%3}, [%4];" \
        : "=r"((R)[0]), "=r"((R)[1]), "=r"((R)[2]), "=r"((R)[3]) : "r"(A))
#define LDSM4T(R, A) \
    asm volatile("ldmatrix.sync.aligned.m8n8.x4.trans.shared.b16 {%0,%1,%2,%3}, [%4];" \
        : "=r"((R)[0]), "=r"((R)[1]), "=r"((R)[2]), "=r"((R)[3]) : "r"(A))
#define MMA16816(C, A, B0, B1) \
    asm volatile("mma.sync.aligned.m16n8k16.row.col.f32.f16.f16.f32 " \
        "{%0,%1,%2,%3}, {%4,%5,%6,%7}, {%8,%9}, {%0,%1,%2,%3};" \
        : "+f"((C)[0]), "+f"((C)[1]), "+f"((C)[2]), "+f"((C)[3]) \
        : "r"((A)[0]), "r"((A)[1]), "r"((A)[2]), "r"((A)[3]), "r"(B0), "r"(B1))

// ---------------- transpose points2 [B,D,S] -> [B,S,D] ----------------
__global__ void transpose_p2_kernel(const float* __restrict__ p2) {
    __shared__ float t[32][33];
    int b = blockIdx.z, s0 = blockIdx.x * 32, d0 = blockIdx.y * 32;
    int tx = threadIdx.x, ty = threadIdx.y;
    const float* src = p2 + (size_t)b * Dfeat * Spts;
#pragma unroll
    for (int j = 0; j < 32; j += 8)
        t[ty + j][tx] = src[(size_t)(d0 + ty + j) * Spts + s0 + tx];
    __syncthreads();
    float* dst = g_p2t + (size_t)b * Spts * Dfeat;
#pragma unroll
    for (int j = 0; j < 32; j += 8)
        dst[(size_t)(s0 + ty + j) * Dfeat + d0 + tx] = t[tx][ty + j];
}

// ---------------- 3-NN + inverse-distance weights ----------------
__global__ void knn_kernel(const float* __restrict__ xyz1, const float* __restrict__ xyz2) {
    __shared__ float4 sP[Spts];    // {-2x, -2y, -2z, |x|^2}
    int b = blockIdx.y;
    int n = blockIdx.x * blockDim.x + threadIdx.x;
    const float* x2 = xyz2 + (size_t)b * 3 * Spts;
    for (int s = threadIdx.x; s < Spts; s += blockDim.x) {
        float X = x2[s], Y = x2[Spts + s], Z = x2[2 * Spts + s];
        sP[s] = make_float4(-2.f * X, -2.f * Y, -2.f * Z, X * X + Y * Y + Z * Z);
    }
    __syncthreads();
    const float* x1 = xyz1 + (size_t)b * 3 * Npts;
    float px = x1[n], py = x1[Npts + n], pz = x1[2 * Npts + n];
    float n1 = px * px + py * py + pz * pz;
    float d0 = 3.4e38f, d1 = 3.4e38f, d2 = 3.4e38f;
    int   i0 = 0, i1 = 0, i2 = 0;
#pragma unroll 8
    for (int s = 0; s < Spts; s++) {
        float4 q = sP[s];
        float d = fmaf(q.x, px, fmaf(q.y, py, fmaf(q.z, pz, q.w)));
        if (d < d2) {
            if (d < d1) {
                d2 = d1; i2 = i1;
                if (d < d0) { d1 = d0; i1 = i0; d0 = d; i0 = s; }
                else        { d1 = d;  i1 = s; }
            } else { d2 = d; i2 = s; }
        }
    }
    float r0 = 1.0f / (d0 + n1 + 1e-8f);
    float r1 = 1.0f / (d1 + n1 + 1e-8f);
    float r2 = 1.0f / (d2 + n1 + 1e-8f);
    float rs = 1.0f / (r0 + r1 + r2);
    int o = (b * Npts + n) * 3;
    g_w3[o] = r0 * rs; g_w3[o + 1] = r1 * rs; g_w3[o + 2] = r2 * rs;
    g_i3[o] = i0;      g_i3[o + 1] = i1;      g_i3[o + 2] = i2;
}

// ---------------- interpolation -> g_ih [B,D,N] fp16 ----------------
__global__ void interp_kernel() {
    __shared__ float tile[256 * 33];
    int b   = blockIdx.y;
    int n0  = blockIdx.x * 32;
    int tid = threadIdx.x, lane = tid & 31, wid = tid >> 5;
#pragma unroll
    for (int p = 0; p < 4; p++) {
        int nloc = wid * 4 + p;
        int n    = n0 + nloc;
        int base = (b * Npts + n) * 3;
        float w0 = g_w3[base], w1 = g_w3[base + 1], w2 = g_w3[base + 2];
        const float* r0 = g_p2t + ((size_t)b * Spts + g_i3[base])     * Dfeat;
        const float* r1 = g_p2t + ((size_t)b * Spts + g_i3[base + 1]) * Dfeat;
        const float* r2 = g_p2t + ((size_t)b * Spts + g_i3[base + 2]) * Dfeat;
#pragma unroll
        for (int j = 0; j < 8; j++) {
            int d = lane + 32 * j;
            tile[d * 33 + nloc] = w0 * r0[d] + w1 * r1[d] + w2 * r2[d];
        }
    }
    __syncthreads();
    __half* outb = g_ih + (size_t)b * Dfeat * Npts;
#pragma unroll 4
    for (int e = tid; e < 256 * 32; e += 256) {
        int d = e >> 5, nl = e & 31;
        outb[(size_t)d * Npts + n0 + nl] = __float2half_rn(tile[d * 33 + nl]);
    }
}

// ---------------- weight split fp32 -> fp16 hi/lo ----------------
__global__ void split_w_kernel(const float* __restrict__ src, int which, int n) {
    int i = blockIdx.x * 256 + threadIdx.x;
    if (i >= n) return;
    float v = src[i];
    __half h = __float2half_rn(v);
    __half l = __float2half_rn(v - __half2float(h));
    if (which) { g_w1h[i] = h; g_w1l[i] = l; }
    else       { g_w0h[i] = h; g_w0l[i] = l; }
}

// ---------------- stats zero / finalize ----------------
__global__ void zero_stats_kernel() {
    int t = threadIdx.x;
    g_sum0[t] = 0.f; g_sq0[t] = 0.f; g_sum1[t] = 0.f; g_sq1[t] = 0.f;
}
__global__ void finalize0_kernel(const float* __restrict__ g, const float* __restrict__ be) {
    int c = threadIdx.x;
    float mean = g_sum0[c] * CNT_INV;
    float var  = g_sq0[c] * CNT_INV - mean * mean;
    float a    = g[c] * rsqrtf(var + 1e-5f);
    g_a0[c] = a; g_be0[c] = be[c] - mean * a;
}
__global__ void finalize1_kernel(const float* __restrict__ g, const float* __restrict__ be) {
    int c = threadIdx.x;
    float mean = g_sum1[c] * CNT_INV;
    float var  = g_sq1[c] * CNT_INV - mean * mean;
    float a    = g[c] * rsqrtf(var + 1e-5f);
    g_a1[c] = a; g_be1[c] = be[c] - mean * a;
}

// ---------------- fp16 2-term HMMA GEMM (R11 structure + B register prefetch) ----------
// CTA tile 128M x 128N, K-chunk 32, 256 thr, 2 CTA/SM. B(c+1) is prefetched into
// registers AFTER the second sync and BEFORE MMA(c) so its DRAM latency overlaps
// tensor work; the fp32->fp16 / BN1+ReLU transform is applied at store time.
#define APAD 40
#define BPAD 136
__global__ __launch_bounds__(256, 2)
void gemm_mma_kernel(int which, const float* __restrict__ p1, float* __restrict__ outp) {
    __shared__ __half sAh[128 * APAD];
    __shared__ __half sAl[128 * APAD];
    __shared__ __half sB[32 * BPAD];

    const int K   = which ? CMID : CIN;
    const int nc  = K / 32;
    const int tid = threadIdx.x;
    const int lane = tid & 31, warp = tid >> 5;
    const int b  = blockIdx.z;
    const int m0 = blockIdx.x * 128;   // x fastest: CTAs sharing an n-panel are adjacent
    const int n0 = blockIdx.y * 128;
    const int wm = (warp >> 1) * 32;
    const int wn = (warp & 1) * 64;

    const __half* Wh = which ? g_w1h : g_w0h;
    const __half* Wl = which ? g_w1l : g_w0l;
    float* sum = which ? g_sum1 : g_sum0;
    float* sq  = which ? g_sq1  : g_sq0;

    float acc[2][8][4];
#pragma unroll
    for (int t = 0; t < 2; t++)
#pragma unroll
        for (int j = 0; j < 8; j++)
#pragma unroll
            for (int q = 0; q < 4; q++) acc[t][j][q] = 0.f;

    const uint32_t uAh = smem_u32(sAh), uAl = smem_u32(sAl);
    const uint32_t uB  = smem_u32(sB);
    const int a_row = wm + (lane & 15);
    const int a_col = (lane >> 4) * 8;
    const int b_row = (lane & 15);
    const int b_col = wn + (lane >> 4) * 8;

    // B staging geometry: per i in {0,1}: row r = (i*256+tid)>>4, col cc = ((i*256+tid)&15)*8
    // Prefetch state (raw, untransformed):
    uint4 brA[2], brB[2];        // brB only used on the fp32 (points1) chunks
    float bnA[2], bnB[2];        // BN1 coefficients for which==1

    auto prefetch_b = [&](int c) {
#pragma unroll
        for (int i = 0; i < 2; i++) {
            int idx = i * 256 + tid;
            int r = idx >> 4, cc = (idx & 15) * 8;
            int k = c * 32 + r;
            size_t coloff = (size_t)n0 + cc;
            if (which) {
                brA[i] = *(const uint4*)(g_y0h + ((size_t)b * CMID + k) * Npts + coloff);
                bnA[i] = g_a0[k]; bnB[i] = g_be0[k];
            } else if (k < Dfeat) {
                const float* src = p1 + ((size_t)b * Dfeat + k) * Npts + coloff;
                brA[i] = *(const uint4*)src;
                brB[i] = *(const uint4*)(src + 4);
            } else {
                brA[i] = *(const uint4*)(g_ih + ((size_t)b * Dfeat + (k - Dfeat)) * Npts + coloff);
            }
        }
    };
    auto store_b = [&](int c) {
#pragma unroll
        for (int i = 0; i < 2; i++) {
            int idx = i * 256 + tid;
            int r = idx >> 4, cc = (idx & 15) * 8;
            uint4 pk;
            if (which) {
                uint4 raw = brA[i];
                float a = bnA[i], be = bnB[i];
                __half2* hp = (__half2*)&raw;
#pragma unroll
                for (int j = 0; j < 4; j++) {
                    float2 f = __half22float2(hp[j]);
                    f.x = fmaxf(fmaf(a, f.x, be), 0.f);
                    f.y = fmaxf(fmaf(a, f.y, be), 0.f);
                    hp[j] = __floats2half2_rn(f.x, f.y);
                }
                pk = raw;
            } else if (c * 32 < Dfeat) {     // chunk-uniform: fp32 points1 rows
                float4 v0 = *(float4*)&brA[i];
                float4 v1 = *(float4*)&brB[i];
                __half2 h0 = __floats2half2_rn(v0.x, v0.y);
                __half2 h1 = __floats2half2_rn(v0.z, v0.w);
                __half2 h2 = __floats2half2_rn(v1.x, v1.y);
                __half2 h3 = __floats2half2_rn(v1.z, v1.w);
                pk = make_uint4(*(uint32_t*)&h0, *(uint32_t*)&h1,
                                *(uint32_t*)&h2, *(uint32_t*)&h3);
            } else {
                pk = brA[i];
            }
            *(uint4*)&sB[r * BPAD + cc] = pk;
        }
    };

    prefetch_b(0);

    for (int c = 0; c < nc; c++) {
        int k0 = c * 32;
        __syncthreads();
        // ---- stage A (weights fp16 hi/lo; L2-hot, covered by co-resident CTA) ----
#pragma unroll
        for (int i = 0; i < 2; i++) {
            int idx = i * 256 + tid;
            int r = idx >> 2, q = (idx & 3) * 8;
            size_t go = (size_t)(m0 + r) * K + k0 + q;
            *(uint4*)&sAh[r * APAD + q] = *(const uint4*)(Wh + go);
            *(uint4*)&sAl[r * APAD + q] = *(const uint4*)(Wl + go);
        }
        // ---- store prefetched B (data already arrived; transform is pure ALU) ----
        store_b(c);
        __syncthreads();
        // ---- issue next B loads BEFORE MMA so DRAM latency hides under tensor work ----
        if (c + 1 < nc) prefetch_b(c + 1);
        // ---- MMA: Wh*B + Wl*B ----
#pragma unroll
        for (int ks = 0; ks < 2; ks++) {
            uint32_t ah[2][4], al[2][4];
#pragma unroll
            for (int t = 0; t < 2; t++) {
                uint32_t adr = uAh + (uint32_t)(((a_row + t * 16) * APAD + ks * 16 + a_col) * 2);
                LDSM4(ah[t], adr);
                adr = uAl + (uint32_t)(((a_row + t * 16) * APAD + ks * 16 + a_col) * 2);
                LDSM4(al[t], adr);
            }
#pragma unroll
            for (int jn = 0; jn < 4; jn++) {
                uint32_t bh[4];
                uint32_t badr = uB + (uint32_t)(((ks * 16 + b_row) * BPAD + b_col + jn * 16) * 2);
                LDSM4T(bh, badr);
                MMA16816(acc[0][jn * 2],     ah[0], bh[0], bh[1]);
                MMA16816(acc[1][jn * 2],     ah[1], bh[0], bh[1]);
                MMA16816(acc[0][jn * 2 + 1], ah[0], bh[2], bh[3]);
                MMA16816(acc[1][jn * 2 + 1], ah[1], bh[2], bh[3]);
                MMA16816(acc[0][jn * 2],     al[0], bh[0], bh[1]);
                MMA16816(acc[1][jn * 2],     al[1], bh[0], bh[1]);
                MMA16816(acc[0][jn * 2 + 1], al[0], bh[2], bh[3]);
                MMA16816(acc[1][jn * 2 + 1], al[1], bh[2], bh[3]);
            }
        }
    }

    // ---- epilogue: store (fp16 y0 | fp32 out) + fused per-channel stats ----
    const int gr = lane >> 2, qc = (lane & 3) * 2;
#pragma unroll
    for (int t = 0; t < 2; t++) {
        int ch0 = m0 + wm + t * 16 + gr;          // rows ch0 and ch0+8
        float s0 = 0.f, q0 = 0.f, s1 = 0.f, q1 = 0.f;
        size_t col = (size_t)n0 + wn + qc;
#pragma unroll
        for (int j = 0; j < 8; j++) {
            float2 v = {acc[t][j][0], acc[t][j][1]};
            float2 w = {acc[t][j][2], acc[t][j][3]};
            s0 += v.x + v.y; q0 += v.x * v.x + v.y * v.y;
            s1 += w.x + w.y; q1 += w.x * w.x + w.y * w.y;
            if (which) {
                float* p0 = outp + ((size_t)b * 256 + ch0) * Npts + col + j * 8;
                *(float2*)p0 = v;
                *(float2*)(p0 + 8 * (size_t)Npts) = w;
            } else {
                __half* p0 = g_y0h + ((size_t)b * 256 + ch0) * Npts + col + j * 8;
                *(__half2*)p0 = __floats2half2_rn(v.x, v.y);
                *(__half2*)(p0 + 8 * (size_t)Npts) = __floats2half2_rn(w.x, w.y);
            }
        }
#pragma unroll
        for (int o = 1; o < 4; o <<= 1) {
            s0 += __shfl_xor_sync(0xffffffffu, s0, o);
            q0 += __shfl_xor_sync(0xffffffffu, q0, o);
            s1 += __shfl_xor_sync(0xffffffffu, s1, o);
            q1 += __shfl_xor_sync(0xffffffffu, q1, o);
        }
        if ((lane & 3) == 0) {
            atomicAdd(sum + ch0, s0);      atomicAdd(sq + ch0, q0);
            atomicAdd(sum + ch0 + 8, s1);  atomicAdd(sq + ch0 + 8, q1);
        }
    }
}

// ---------------- final BN2 + ReLU in place on d_out ----------------
__global__ void bnrelu_kernel(float* __restrict__ out) {
    size_t i = (size_t)blockIdx.x * 256 + threadIdx.x;   // float4 index
    int c = (int)((i / (Npts / 4)) & (COUT - 1));
    float a = g_a1[c], be = g_be1[c];
    float4 v = ((float4*)out)[i];
    v.x = fmaxf(fmaf(a, v.x, be), 0.f);
    v.y = fmaxf(fmaf(a, v.y, be), 0.f);
    v.z = fmaxf(fmaf(a, v.z, be), 0.f);
    v.w = fmaxf(fmaf(a, v.w, be), 0.f);
    ((float4*)out)[i] = v;
}

// ---------------- launch ----------------
extern "C" void kernel_launch(void* const* d_in, const int* in_sizes, int n_in,
                              void* d_out, int out_size) {
    const float* xyz1    = (const float*)d_in[0];
    const float* xyz2    = (const float*)d_in[1];
    const float* points1 = (const float*)d_in[2];
    const float* points2 = (const float*)d_in[3];
    const float* w0      = (const float*)d_in[4];
    const float* g0      = (const float*)d_in[6];
    const float* be0     = (const float*)d_in[7];
    const float* w1      = (const float*)d_in[8];
    const float* g1      = (const float*)d_in[10];
    const float* be1     = (const float*)d_in[11];
    float* out = (float*)d_out;

    split_w_kernel<<<(CMID * CIN + 255) / 256, 256>>>(w0, 0, CMID * CIN);
    split_w_kernel<<<(COUT * CMID + 255) / 256, 256>>>(w1, 1, COUT * CMID);
    transpose_p2_kernel<<<dim3(Spts / 32, Dfeat / 32, Bsz), dim3(32, 8)>>>(points2);
    knn_kernel<<<dim3(Npts / 256, Bsz), 256>>>(xyz1, xyz2);
    interp_kernel<<<dim3(Npts / 32, Bsz), 256>>>();
    zero_stats_kernel<<<1, 256>>>();
    gemm_mma_kernel<<<dim3(2, Npts / 128, Bsz), 256>>>(0, points1, out);
    finalize0_kernel<<<1, CMID>>>(g0, be0);
    gemm_mma_kernel<<<dim3(2, Npts / 128, Bsz), 256>>>(1, points1, out);
    finalize1_kernel<<<1, COUT>>>(g1, be1);
    bnrelu_kernel<<<(int)(((size_t)Bsz * COUT * Npts / 4) / 256), 256>>>(out);
}

// round 15
// speedup vs baseline: 1.3578x; 1.2005x over previous
#include <cuda_runtime.h>
#include <cuda_fp16.h>
#include <cstdint>

#define Bsz   8
#define Npts  16384
#define Spts  1024
#define Dfeat 256
#define CIN   512
#define CMID  256
#define COUT  256
#define CNT_INV (1.0f / (8.0f * 16384.0f))

// ---------------- scratch (device globals; no runtime allocation) ----------------
__device__ __align__(128) float g_p2t[Bsz * Spts * Dfeat];            // points2^T [B,S,D]
__device__ float g_w3[Bsz * Npts * 3];
__device__ int   g_i3[Bsz * Npts * 3];
__device__ __align__(128) __half g_ih[(size_t)Bsz * Dfeat * Npts];    // interp [B,D,N] fp16
__device__ __align__(128) __half g_y0h[(size_t)Bsz * CMID * Npts];    // raw GEMM1 out fp16
__device__ __align__(128) __half g_w0h[CMID * CIN];                   // GEMM1: hi only
__device__ __align__(128) __half g_w1h[COUT * CMID], g_w1l[COUT * CMID];
__device__ float g_sum0[CMID], g_sq0[CMID], g_sum1[COUT], g_sq1[COUT];
__device__ float g_a0[CMID], g_be0[CMID], g_a1[COUT], g_be1[COUT];

// ---------------- helpers ----------------
__device__ __forceinline__ uint32_t smem_u32(const void* p) {
    uint32_t a;
    asm("{ .reg .u64 t; cvta.to.shared.u64 t, %1; cvt.u32.u64 %0, t; }" : "=r"(a) : "l"(p));
    return a;
}
#define LDSM4(R, A) \
    asm volatile("ldmatrix.sync.aligned.m8n8.x4.shared.b16 {%0,%1,%2,%3}, [%4];" \
        : "=r"((R)[0]), "=r"((R)[1]), "=r"((R)[2]), "=r"((R)[3]) : "r"(A))
#define LDSM4T(R, A) \
    asm volatile("ldmatrix.sync.aligned.m8n8.x4.trans.shared.b16 {%0,%1,%2,%3}, [%4];" \
        : "=r"((R)[0]), "=r"((R)[1]), "=r"((R)[2]), "=r"((R)[3]) : "r"(A))
#define MMA16816(C, A, B0, B1) \
    asm volatile("mma.sync.aligned.m16n8k16.row.col.f32.f16.f16.f32 " \
        "{%0,%1,%2,%3}, {%4,%5,%6,%7}, {%8,%9}, {%0,%1,%2,%3};" \
        : "+f"((C)[0]), "+f"((C)[1]), "+f"((C)[2]), "+f"((C)[3]) \
        : "r"((A)[0]), "r"((A)[1]), "r"((A)[2]), "r"((A)[3]), "r"(B0), "r"(B1))

// ---------------- transpose points2 [B,D,S] -> [B,S,D] ----------------
__global__ void transpose_p2_kernel(const float* __restrict__ p2) {
    __shared__ float t[32][33];
    int b = blockIdx.z, s0 = blockIdx.x * 32, d0 = blockIdx.y * 32;
    int tx = threadIdx.x, ty = threadIdx.y;
    const float* src = p2 + (size_t)b * Dfeat * Spts;
#pragma unroll
    for (int j = 0; j < 32; j += 8)
        t[ty + j][tx] = src[(size_t)(d0 + ty + j) * Spts + s0 + tx];
    __syncthreads();
    float* dst = g_p2t + (size_t)b * Spts * Dfeat;
#pragma unroll
    for (int j = 0; j < 32; j += 8)
        dst[(size_t)(s0 + ty + j) * Dfeat + d0 + tx] = t[tx][ty + j];
}

// ---------------- 3-NN + inverse-distance weights ----------------
__global__ void knn_kernel(const float* __restrict__ xyz1, const float* __restrict__ xyz2) {
    __shared__ float4 sP[Spts];    // {-2x, -2y, -2z, |x|^2}
    int b = blockIdx.y;
    int n = blockIdx.x * blockDim.x + threadIdx.x;
    const float* x2 = xyz2 + (size_t)b * 3 * Spts;
    for (int s = threadIdx.x; s < Spts; s += blockDim.x) {
        float X = x2[s], Y = x2[Spts + s], Z = x2[2 * Spts + s];
        sP[s] = make_float4(-2.f * X, -2.f * Y, -2.f * Z, X * X + Y * Y + Z * Z);
    }
    __syncthreads();
    const float* x1 = xyz1 + (size_t)b * 3 * Npts;
    float px = x1[n], py = x1[Npts + n], pz = x1[2 * Npts + n];
    float n1 = px * px + py * py + pz * pz;
    float d0 = 3.4e38f, d1 = 3.4e38f, d2 = 3.4e38f;
    int   i0 = 0, i1 = 0, i2 = 0;
#pragma unroll 8
    for (int s = 0; s < Spts; s++) {
        float4 q = sP[s];
        float d = fmaf(q.x, px, fmaf(q.y, py, fmaf(q.z, pz, q.w)));
        if (d < d2) {
            if (d < d1) {
                d2 = d1; i2 = i1;
                if (d < d0) { d1 = d0; i1 = i0; d0 = d; i0 = s; }
                else        { d1 = d;  i1 = s; }
            } else { d2 = d; i2 = s; }
        }
    }
    float r0 = 1.0f / (d0 + n1 + 1e-8f);
    float r1 = 1.0f / (d1 + n1 + 1e-8f);
    float r2 = 1.0f / (d2 + n1 + 1e-8f);
    float rs = 1.0f / (r0 + r1 + r2);
    int o = (b * Npts + n) * 3;
    g_w3[o] = r0 * rs; g_w3[o + 1] = r1 * rs; g_w3[o + 2] = r2 * rs;
    g_i3[o] = i0;      g_i3[o + 1] = i1;      g_i3[o + 2] = i2;
}

// ---------------- interpolation -> g_ih [B,D,N] fp16 ----------------
__global__ void interp_kernel() {
    __shared__ float tile[256 * 33];
    int b   = blockIdx.y;
    int n0  = blockIdx.x * 32;
    int tid = threadIdx.x, lane = tid & 31, wid = tid >> 5;
#pragma unroll
    for (int p = 0; p < 4; p++) {
        int nloc = wid * 4 + p;
        int n    = n0 + nloc;
        int base = (b * Npts + n) * 3;
        float w0 = g_w3[base], w1 = g_w3[base + 1], w2 = g_w3[base + 2];
        const float* r0 = g_p2t + ((size_t)b * Spts + g_i3[base])     * Dfeat;
        const float* r1 = g_p2t + ((size_t)b * Spts + g_i3[base + 1]) * Dfeat;
        const float* r2 = g_p2t + ((size_t)b * Spts + g_i3[base + 2]) * Dfeat;
#pragma unroll
        for (int j = 0; j < 8; j++) {
            int d = lane + 32 * j;
            tile[d * 33 + nloc] = w0 * r0[d] + w1 * r1[d] + w2 * r2[d];
        }
    }
    __syncthreads();
    __half* outb = g_ih + (size_t)b * Dfeat * Npts;
#pragma unroll 4
    for (int e = tid; e < 256 * 32; e += 256) {
        int d = e >> 5, nl = e & 31;
        outb[(size_t)d * Npts + n0 + nl] = __float2half_rn(tile[d * 33 + nl]);
    }
}

// ---------------- weight prep ----------------
__global__ void split_w0_kernel(const float* __restrict__ src) {   // hi only
    int i = blockIdx.x * 256 + threadIdx.x;
    if (i < CMID * CIN) g_w0h[i] = __float2half_rn(src[i]);
}
__global__ void split_w1_kernel(const float* __restrict__ src) {   // hi + lo
    int i = blockIdx.x * 256 + threadIdx.x;
    if (i >= COUT * CMID) return;
    float v = src[i];
    __half h = __float2half_rn(v);
    g_w1h[i] = h;
    g_w1l[i] = __float2half_rn(v - __half2float(h));
}

// ---------------- stats zero / finalize ----------------
__global__ void zero_stats_kernel() {
    int t = threadIdx.x;
    g_sum0[t] = 0.f; g_sq0[t] = 0.f; g_sum1[t] = 0.f; g_sq1[t] = 0.f;
}
__global__ void finalize0_kernel(const float* __restrict__ g, const float* __restrict__ be) {
    int c = threadIdx.x;
    float mean = g_sum0[c] * CNT_INV;
    float var  = g_sq0[c] * CNT_INV - mean * mean;
    float a    = g[c] * rsqrtf(var + 1e-5f);
    g_a0[c] = a; g_be0[c] = be[c] - mean * a;
}
__global__ void finalize1_kernel(const float* __restrict__ g, const float* __restrict__ be) {
    int c = threadIdx.x;
    float mean = g_sum1[c] * CNT_INV;
    float var  = g_sq1[c] * CNT_INV - mean * mean;
    float a    = g[c] * rsqrtf(var + 1e-5f);
    g_a1[c] = a; g_be1[c] = be[c] - mean * a;
}

// ---------------- fp16 HMMA GEMM (templated: WHICH=0 single-term, WHICH=1 two-term) ----
// CTA tile 128M x 128N, K-chunk 32, 256 thr, 2 CTA/SM. B(c+1) register-prefetched
// before MMA(c); transform applied at store time.
#define APAD 40
#define BPAD 136
template <int WHICH>
__global__ __launch_bounds__(256, 2)
void gemm_mma_kernel(const float* __restrict__ p1, float* __restrict__ outp) {
    __shared__ __half sAh[128 * APAD];
    __shared__ __half sAl[WHICH ? 128 * APAD : 1];
    __shared__ __half sB[32 * BPAD];

    const int K   = WHICH ? CMID : CIN;
    const int nc  = K / 32;
    const int tid = threadIdx.x;
    const int lane = tid & 31, warp = tid >> 5;
    const int b  = blockIdx.z;
    const int m0 = blockIdx.x * 128;   // x fastest: CTAs sharing an n-panel are adjacent
    const int n0 = blockIdx.y * 128;
    const int wm = (warp >> 1) * 32;
    const int wn = (warp & 1) * 64;

    const __half* Wh = WHICH ? g_w1h : g_w0h;
    const __half* Wl = WHICH ? g_w1l : g_w0h;   // unused when WHICH==0
    float* sum = WHICH ? g_sum1 : g_sum0;
    float* sq  = WHICH ? g_sq1  : g_sq0;

    float acc[2][8][4];
#pragma unroll
    for (int t = 0; t < 2; t++)
#pragma unroll
        for (int j = 0; j < 8; j++)
#pragma unroll
            for (int q = 0; q < 4; q++) acc[t][j][q] = 0.f;

    const uint32_t uAh = smem_u32(sAh), uAl = smem_u32(sAl);
    const uint32_t uB  = smem_u32(sB);
    const int a_row = wm + (lane & 15);
    const int a_col = (lane >> 4) * 8;
    const int b_row = (lane & 15);
    const int b_col = wn + (lane >> 4) * 8;

    // B prefetch state (raw, untransformed)
    uint4 brA[2], brB[2];
    float bnA[2], bnB[2];

    auto prefetch_b = [&](int c) {
#pragma unroll
        for (int i = 0; i < 2; i++) {
            int idx = i * 256 + tid;
            int r = idx >> 4, cc = (idx & 15) * 8;
            int k = c * 32 + r;
            size_t coloff = (size_t)n0 + cc;
            if (WHICH) {
                brA[i] = *(const uint4*)(g_y0h + ((size_t)b * CMID + k) * Npts + coloff);
                bnA[i] = g_a0[k]; bnB[i] = g_be0[k];
            } else if (k < Dfeat) {
                const float* src = p1 + ((size_t)b * Dfeat + k) * Npts + coloff;
                brA[i] = *(const uint4*)src;
                brB[i] = *(const uint4*)(src + 4);
            } else {
                brA[i] = *(const uint4*)(g_ih + ((size_t)b * Dfeat + (k - Dfeat)) * Npts + coloff);
            }
        }
    };
    auto store_b = [&](int c) {
#pragma unroll
        for (int i = 0; i < 2; i++) {
            int idx = i * 256 + tid;
            int r = idx >> 4, cc = (idx & 15) * 8;
            uint4 pk;
            if (WHICH) {
                uint4 raw = brA[i];
                float a = bnA[i], be = bnB[i];
                __half2* hp = (__half2*)&raw;
#pragma unroll
                for (int j = 0; j < 4; j++) {
                    float2 f = __half22float2(hp[j]);
                    f.x = fmaxf(fmaf(a, f.x, be), 0.f);
                    f.y = fmaxf(fmaf(a, f.y, be), 0.f);
                    hp[j] = __floats2half2_rn(f.x, f.y);
                }
                pk = raw;
            } else if (c * 32 < Dfeat) {     // chunk-uniform: fp32 points1 rows
                float4 v0 = *(float4*)&brA[i];
                float4 v1 = *(float4*)&brB[i];
                __half2 h0 = __floats2half2_rn(v0.x, v0.y);
                __half2 h1 = __floats2half2_rn(v0.z, v0.w);
                __half2 h2 = __floats2half2_rn(v1.x, v1.y);
                __half2 h3 = __floats2half2_rn(v1.z, v1.w);
                pk = make_uint4(*(uint32_t*)&h0, *(uint32_t*)&h1,
                                *(uint32_t*)&h2, *(uint32_t*)&h3);
            } else {
                pk = brA[i];
            }
            *(uint4*)&sB[r * BPAD + cc] = pk;
        }
    };

    prefetch_b(0);

    for (int c = 0; c < nc; c++) {
        int k0 = c * 32;
        __syncthreads();
        // ---- stage A (hi always; lo only for WHICH==1) ----
#pragma unroll
        for (int i = 0; i < 2; i++) {
            int idx = i * 256 + tid;
            int r = idx >> 2, q = (idx & 3) * 8;
            size_t go = (size_t)(m0 + r) * K + k0 + q;
            *(uint4*)&sAh[r * APAD + q] = *(const uint4*)(Wh + go);
            if (WHICH)
                *(uint4*)&sAl[r * APAD + q] = *(const uint4*)(Wl + go);
        }
        store_b(c);
        __syncthreads();
        if (c + 1 < nc) prefetch_b(c + 1);
        // ---- MMA ----
#pragma unroll
        for (int ks = 0; ks < 2; ks++) {
            uint32_t ah[2][4], al[2][4];
#pragma unroll
            for (int t = 0; t < 2; t++) {
                uint32_t adr = uAh + (uint32_t)(((a_row + t * 16) * APAD + ks * 16 + a_col) * 2);
                LDSM4(ah[t], adr);
                if (WHICH) {
                    adr = uAl + (uint32_t)(((a_row + t * 16) * APAD + ks * 16 + a_col) * 2);
                    LDSM4(al[t], adr);
                }
            }
#pragma unroll
            for (int jn = 0; jn < 4; jn++) {
                uint32_t bh[4];
                uint32_t badr = uB + (uint32_t)(((ks * 16 + b_row) * BPAD + b_col + jn * 16) * 2);
                LDSM4T(bh, badr);
                MMA16816(acc[0][jn * 2],     ah[0], bh[0], bh[1]);
                MMA16816(acc[1][jn * 2],     ah[1], bh[0], bh[1]);
                MMA16816(acc[0][jn * 2 + 1], ah[0], bh[2], bh[3]);
                MMA16816(acc[1][jn * 2 + 1], ah[1], bh[2], bh[3]);
                if (WHICH) {
                    MMA16816(acc[0][jn * 2],     al[0], bh[0], bh[1]);
                    MMA16816(acc[1][jn * 2],     al[1], bh[0], bh[1]);
                    MMA16816(acc[0][jn * 2 + 1], al[0], bh[2], bh[3]);
                    MMA16816(acc[1][jn * 2 + 1], al[1], bh[2], bh[3]);
                }
            }
        }
    }

    // ---- epilogue: store (fp16 y0 | fp32 out) + fused per-channel stats ----
    const int gr = lane >> 2, qc = (lane & 3) * 2;
#pragma unroll
    for (int t = 0; t < 2; t++) {
        int ch0 = m0 + wm + t * 16 + gr;          // rows ch0 and ch0+8
        float s0 = 0.f, q0 = 0.f, s1 = 0.f, q1 = 0.f;
        size_t col = (size_t)n0 + wn + qc;
#pragma unroll
        for (int j = 0; j < 8; j++) {
            float2 v = {acc[t][j][0], acc[t][j][1]};
            float2 w = {acc[t][j][2], acc[t][j][3]};
            s0 += v.x + v.y; q0 += v.x * v.x + v.y * v.y;
            s1 += w.x + w.y; q1 += w.x * w.x + w.y * w.y;
            if (WHICH) {
                float* p0 = outp + ((size_t)b * 256 + ch0) * Npts + col + j * 8;
                *(float2*)p0 = v;
                *(float2*)(p0 + 8 * (size_t)Npts) = w;
            } else {
                __half* p0 = g_y0h + ((size_t)b * 256 + ch0) * Npts + col + j * 8;
                *(__half2*)p0 = __floats2half2_rn(v.x, v.y);
                *(__half2*)(p0 + 8 * (size_t)Npts) = __floats2half2_rn(w.x, w.y);
            }
        }
#pragma unroll
        for (int o = 1; o < 4; o <<= 1) {
            s0 += __shfl_xor_sync(0xffffffffu, s0, o);
            q0 += __shfl_xor_sync(0xffffffffu, q0, o);
            s1 += __shfl_xor_sync(0xffffffffu, s1, o);
            q1 += __shfl_xor_sync(0xffffffffu, q1, o);
        }
        if ((lane & 3) == 0) {
            atomicAdd(sum + ch0, s0);      atomicAdd(sq + ch0, q0);
            atomicAdd(sum + ch0 + 8, s1);  atomicAdd(sq + ch0 + 8, q1);
        }
    }
}

// ---------------- final BN2 + ReLU in place on d_out ----------------
__global__ void bnrelu_kernel(float* __restrict__ out) {
    size_t i = (size_t)blockIdx.x * 256 + threadIdx.x;   // float4 index
    int c = (int)((i / (Npts / 4)) & (COUT - 1));
    float a = g_a1[c], be = g_be1[c];
    float4 v = ((float4*)out)[i];
    v.x = fmaxf(fmaf(a, v.x, be), 0.f);
    v.y = fmaxf(fmaf(a, v.y, be), 0.f);
    v.z = fmaxf(fmaf(a, v.z, be), 0.f);
    v.w = fmaxf(fmaf(a, v.w, be), 0.f);
    ((float4*)out)[i] = v;
}

// ---------------- launch ----------------
extern "C" void kernel_launch(void* const* d_in, const int* in_sizes, int n_in,
                              void* d_out, int out_size) {
    const float* xyz1    = (const float*)d_in[0];
    const float* xyz2    = (const float*)d_in[1];
    const float* points1 = (const float*)d_in[2];
    const float* points2 = (const float*)d_in[3];
    const float* w0      = (const float*)d_in[4];
    const float* g0      = (const float*)d_in[6];
    const float* be0     = (const float*)d_in[7];
    const float* w1      = (const float*)d_in[8];
    const float* g1      = (const float*)d_in[10];
    const float* be1     = (const float*)d_in[11];
    float* out = (float*)d_out;

    split_w0_kernel<<<(CMID * CIN + 255) / 256, 256>>>(w0);
    split_w1_kernel<<<(COUT * CMID + 255) / 256, 256>>>(w1);
    transpose_p2_kernel<<<dim3(Spts / 32, Dfeat / 32, Bsz), dim3(32, 8)>>>(points2);
    knn_kernel<<<dim3(Npts / 256, Bsz), 256>>>(xyz1, xyz2);
    interp_kernel<<<dim3(Npts / 32, Bsz), 256>>>();
    zero_stats_kernel<<<1, 256>>>();
    gemm_mma_kernel<0><<<dim3(2, Npts / 128, Bsz), 256>>>(points1, out);
    finalize0_kernel<<<1, CMID>>>(g0, be0);
    gemm_mma_kernel<1><<<dim3(2, Npts / 128, Bsz), 256>>>(points1, out);
    finalize1_kernel<<<1, COUT>>>(g1, be1);
    bnrelu_kernel<<<(int)(((size_t)Bsz * COUT * Npts / 4) / 256), 256>>>(out);
}

// round 16
// speedup vs baseline: 1.4514x; 1.0689x over previous
#include <cuda_runtime.h>
#include <cuda_fp16.h>
#include <cstdint>

#define Bsz   8
#define Npts  16384
#define Spts  1024
#define Dfeat 256
#define CIN   512
#define CMID  256
#define COUT  256
#define CNT_INV (1.0f / (8.0f * 16384.0f))

// ---------------- scratch (device globals; no runtime allocation) ----------------
__device__ __align__(128) float g_p2t[Bsz * Spts * Dfeat];            // points2^T [B,S,D]
__device__ float g_w3[Bsz * Npts * 3];
__device__ int   g_i3[Bsz * Npts * 3];
__device__ __align__(128) __half g_ih[(size_t)Bsz * Dfeat * Npts];    // interp [B,D,N] fp16
__device__ __align__(128) __half g_y0h[(size_t)Bsz * CMID * Npts];    // raw GEMM1 out fp16
__device__ __align__(128) __half g_w0h[CMID * CIN];                   // fp16 weights (hi only)
__device__ __align__(128) __half g_w1h[COUT * CMID];
__device__ float g_sum0[CMID], g_sq0[CMID], g_sum1[COUT], g_sq1[COUT];
__device__ float g_a0[CMID], g_be0[CMID], g_a1[COUT], g_be1[COUT];

// ---------------- helpers ----------------
__device__ __forceinline__ uint32_t smem_u32(const void* p) {
    uint32_t a;
    asm("{ .reg .u64 t; cvta.to.shared.u64 t, %1; cvt.u32.u64 %0, t; }" : "=r"(a) : "l"(p));
    return a;
}
#define LDSM4(R, A) \
    asm volatile("ldmatrix.sync.aligned.m8n8.x4.shared.b16 {%0,%1,%2,%3}, [%4];" \
        : "=r"((R)[0]), "=r"((R)[1]), "=r"((R)[2]), "=r"((R)[3]) : "r"(A))
#define LDSM4T(R, A) \
    asm volatile("ldmatrix.sync.aligned.m8n8.x4.trans.shared.b16 {%0,%1,%2,%3}, [%4];" \
        : "=r"((R)[0]), "=r"((R)[1]), "=r"((R)[2]), "=r"((R)[3]) : "r"(A))
#define MMA16816(C, A, B0, B1) \
    asm volatile("mma.sync.aligned.m16n8k16.row.col.f32.f16.f16.f32 " \
        "{%0,%1,%2,%3}, {%4,%5,%6,%7}, {%8,%9}, {%0,%1,%2,%3};" \
        : "+f"((C)[0]), "+f"((C)[1]), "+f"((C)[2]), "+f"((C)[3]) \
        : "r"((A)[0]), "r"((A)[1]), "r"((A)[2]), "r"((A)[3]), "r"(B0), "r"(B1))

// ---------------- transpose points2 [B,D,S] -> [B,S,D] ----------------
__global__ void transpose_p2_kernel(const float* __restrict__ p2) {
    __shared__ float t[32][33];
    int b = blockIdx.z, s0 = blockIdx.x * 32, d0 = blockIdx.y * 32;
    int tx = threadIdx.x, ty = threadIdx.y;
    const float* src = p2 + (size_t)b * Dfeat * Spts;
#pragma unroll
    for (int j = 0; j < 32; j += 8)
        t[ty + j][tx] = src[(size_t)(d0 + ty + j) * Spts + s0 + tx];
    __syncthreads();
    float* dst = g_p2t + (size_t)b * Spts * Dfeat;
#pragma unroll
    for (int j = 0; j < 32; j += 8)
        dst[(size_t)(s0 + ty + j) * Dfeat + d0 + tx] = t[tx][ty + j];
}

// ---------------- 3-NN + inverse-distance weights ----------------
__global__ void knn_kernel(const float* __restrict__ xyz1, const float* __restrict__ xyz2) {
    __shared__ float4 sP[Spts];    // {-2x, -2y, -2z, |x|^2}
    int b = blockIdx.y;
    int n = blockIdx.x * blockDim.x + threadIdx.x;
    const float* x2 = xyz2 + (size_t)b * 3 * Spts;
    for (int s = threadIdx.x; s < Spts; s += blockDim.x) {
        float X = x2[s], Y = x2[Spts + s], Z = x2[2 * Spts + s];
        sP[s] = make_float4(-2.f * X, -2.f * Y, -2.f * Z, X * X + Y * Y + Z * Z);
    }
    __syncthreads();
    const float* x1 = xyz1 + (size_t)b * 3 * Npts;
    float px = x1[n], py = x1[Npts + n], pz = x1[2 * Npts + n];
    float n1 = px * px + py * py + pz * pz;
    float d0 = 3.4e38f, d1 = 3.4e38f, d2 = 3.4e38f;
    int   i0 = 0, i1 = 0, i2 = 0;
#pragma unroll 8
    for (int s = 0; s < Spts; s++) {
        float4 q = sP[s];
        float d = fmaf(q.x, px, fmaf(q.y, py, fmaf(q.z, pz, q.w)));
        if (d < d2) {
            if (d < d1) {
                d2 = d1; i2 = i1;
                if (d < d0) { d1 = d0; i1 = i0; d0 = d; i0 = s; }
                else        { d1 = d;  i1 = s; }
            } else { d2 = d; i2 = s; }
        }
    }
    float r0 = 1.0f / (d0 + n1 + 1e-8f);
    float r1 = 1.0f / (d1 + n1 + 1e-8f);
    float r2 = 1.0f / (d2 + n1 + 1e-8f);
    float rs = 1.0f / (r0 + r1 + r2);
    int o = (b * Npts + n) * 3;
    g_w3[o] = r0 * rs; g_w3[o + 1] = r1 * rs; g_w3[o + 2] = r2 * rs;
    g_i3[o] = i0;      g_i3[o + 1] = i1;      g_i3[o + 2] = i2;
}

// ---------------- interpolation -> g_ih [B,D,N] fp16 ----------------
__global__ void interp_kernel() {
    __shared__ float tile[256 * 33];
    int b   = blockIdx.y;
    int n0  = blockIdx.x * 32;
    int tid = threadIdx.x, lane = tid & 31, wid = tid >> 5;
#pragma unroll
    for (int p = 0; p < 4; p++) {
        int nloc = wid * 4 + p;
        int n    = n0 + nloc;
        int base = (b * Npts + n) * 3;
        float w0 = g_w3[base], w1 = g_w3[base + 1], w2 = g_w3[base + 2];
        const float* r0 = g_p2t + ((size_t)b * Spts + g_i3[base])     * Dfeat;
        const float* r1 = g_p2t + ((size_t)b * Spts + g_i3[base + 1]) * Dfeat;
        const float* r2 = g_p2t + ((size_t)b * Spts + g_i3[base + 2]) * Dfeat;
#pragma unroll
        for (int j = 0; j < 8; j++) {
            int d = lane + 32 * j;
            tile[d * 33 + nloc] = w0 * r0[d] + w1 * r1[d] + w2 * r2[d];
        }
    }
    __syncthreads();
    __half* outb = g_ih + (size_t)b * Dfeat * Npts;
#pragma unroll 4
    for (int e = tid; e < 256 * 32; e += 256) {
        int d = e >> 5, nl = e & 31;
        outb[(size_t)d * Npts + n0 + nl] = __float2half_rn(tile[d * 33 + nl]);
    }
}

// ---------------- weight prep (fp16 hi only) ----------------
__global__ void split_w0_kernel(const float* __restrict__ src) {
    int i = blockIdx.x * 256 + threadIdx.x;
    if (i < CMID * CIN) g_w0h[i] = __float2half_rn(src[i]);
}
__global__ void split_w1_kernel(const float* __restrict__ src) {
    int i = blockIdx.x * 256 + threadIdx.x;
    if (i < COUT * CMID) g_w1h[i] = __float2half_rn(src[i]);
}

// ---------------- stats zero / finalize ----------------
__global__ void zero_stats_kernel() {
    int t = threadIdx.x;
    g_sum0[t] = 0.f; g_sq0[t] = 0.f; g_sum1[t] = 0.f; g_sq1[t] = 0.f;
}
__global__ void finalize0_kernel(const float* __restrict__ g, const float* __restrict__ be) {
    int c = threadIdx.x;
    float mean = g_sum0[c] * CNT_INV;
    float var  = g_sq0[c] * CNT_INV - mean * mean;
    float a    = g[c] * rsqrtf(var + 1e-5f);
    g_a0[c] = a; g_be0[c] = be[c] - mean * a;
}
__global__ void finalize1_kernel(const float* __restrict__ g, const float* __restrict__ be) {
    int c = threadIdx.x;
    float mean = g_sum1[c] * CNT_INV;
    float var  = g_sq1[c] * CNT_INV - mean * mean;
    float a    = g[c] * rsqrtf(var + 1e-5f);
    g_a1[c] = a; g_be1[c] = be[c] - mean * a;
}

// ---------------- fp16 HMMA GEMM (WHICH selects src/dst; LO adds weight-lo term) ----
// CTA tile 128M x 128N, K-chunk 32, 256 thr, 2 CTA/SM. B(c+1) register-prefetched
// before MMA(c); transform applied at store time.
#define APAD 40
#define BPAD 136
template <int WHICH, bool LO>
__global__ __launch_bounds__(256, 2)
void gemm_mma_kernel(const float* __restrict__ p1, const __half* __restrict__ Wl,
                     float* __restrict__ outp) {
    __shared__ __half sAh[128 * APAD];
    __shared__ __half sAl[LO ? 128 * APAD : 1];
    __shared__ __half sB[32 * BPAD];

    const int K   = WHICH ? CMID : CIN;
    const int nc  = K / 32;
    const int tid = threadIdx.x;
    const int lane = tid & 31, warp = tid >> 5;
    const int b  = blockIdx.z;
    const int m0 = blockIdx.x * 128;   // x fastest: CTAs sharing an n-panel are adjacent
    const int n0 = blockIdx.y * 128;
    const int wm = (warp >> 1) * 32;
    const int wn = (warp & 1) * 64;

    const __half* Wh = WHICH ? g_w1h : g_w0h;
    float* sum = WHICH ? g_sum1 : g_sum0;
    float* sq  = WHICH ? g_sq1  : g_sq0;

    float acc[2][8][4];
#pragma unroll
    for (int t = 0; t < 2; t++)
#pragma unroll
        for (int j = 0; j < 8; j++)
#pragma unroll
            for (int q = 0; q < 4; q++) acc[t][j][q] = 0.f;

    const uint32_t uAh = smem_u32(sAh), uAl = smem_u32(sAl);
    const uint32_t uB  = smem_u32(sB);
    const int a_row = wm + (lane & 15);
    const int a_col = (lane >> 4) * 8;
    const int b_row = (lane & 15);
    const int b_col = wn + (lane >> 4) * 8;

    // B prefetch state (raw, untransformed)
    uint4 brA[2], brB[2];
    float bnA[2], bnB[2];

    auto prefetch_b = [&](int c) {
#pragma unroll
        for (int i = 0; i < 2; i++) {
            int idx = i * 256 + tid;
            int r = idx >> 4, cc = (idx & 15) * 8;
            int k = c * 32 + r;
            size_t coloff = (size_t)n0 + cc;
            if (WHICH) {
                brA[i] = *(const uint4*)(g_y0h + ((size_t)b * CMID + k) * Npts + coloff);
                bnA[i] = g_a0[k]; bnB[i] = g_be0[k];
            } else if (k < Dfeat) {
                const float* src = p1 + ((size_t)b * Dfeat + k) * Npts + coloff;
                brA[i] = *(const uint4*)src;
                brB[i] = *(const uint4*)(src + 4);
            } else {
                brA[i] = *(const uint4*)(g_ih + ((size_t)b * Dfeat + (k - Dfeat)) * Npts + coloff);
            }
        }
    };
    auto store_b = [&](int c) {
#pragma unroll
        for (int i = 0; i < 2; i++) {
            int idx = i * 256 + tid;
            int r = idx >> 4, cc = (idx & 15) * 8;
            uint4 pk;
            if (WHICH) {
                uint4 raw = brA[i];
                float a = bnA[i], be = bnB[i];
                __half2* hp = (__half2*)&raw;
#pragma unroll
                for (int j = 0; j < 4; j++) {
                    float2 f = __half22float2(hp[j]);
                    f.x = fmaxf(fmaf(a, f.x, be), 0.f);
                    f.y = fmaxf(fmaf(a, f.y, be), 0.f);
                    hp[j] = __floats2half2_rn(f.x, f.y);
                }
                pk = raw;
            } else if (c * 32 < Dfeat) {     // chunk-uniform: fp32 points1 rows
                float4 v0 = *(float4*)&brA[i];
                float4 v1 = *(float4*)&brB[i];
                __half2 h0 = __floats2half2_rn(v0.x, v0.y);
                __half2 h1 = __floats2half2_rn(v0.z, v0.w);
                __half2 h2 = __floats2half2_rn(v1.x, v1.y);
                __half2 h3 = __floats2half2_rn(v1.z, v1.w);
                pk = make_uint4(*(uint32_t*)&h0, *(uint32_t*)&h1,
                                *(uint32_t*)&h2, *(uint32_t*)&h3);
            } else {
                pk = brA[i];
            }
            *(uint4*)&sB[r * BPAD + cc] = pk;
        }
    };

    prefetch_b(0);

    for (int c = 0; c < nc; c++) {
        int k0 = c * 32;
        __syncthreads();
        // ---- stage A (hi always; lo only when LO) ----
#pragma unroll
        for (int i = 0; i < 2; i++) {
            int idx = i * 256 + tid;
            int r = idx >> 2, q = (idx & 3) * 8;
            size_t go = (size_t)(m0 + r) * K + k0 + q;
            *(uint4*)&sAh[r * APAD + q] = *(const uint4*)(Wh + go);
            if (LO)
                *(uint4*)&sAl[r * APAD + q] = *(const uint4*)(Wl + go);
        }
        store_b(c);
        __syncthreads();
        if (c + 1 < nc) prefetch_b(c + 1);
        // ---- MMA ----
#pragma unroll
        for (int ks = 0; ks < 2; ks++) {
            uint32_t ah[2][4], al[2][4];
#pragma unroll
            for (int t = 0; t < 2; t++) {
                uint32_t adr = uAh + (uint32_t)(((a_row + t * 16) * APAD + ks * 16 + a_col) * 2);
                LDSM4(ah[t], adr);
                if (LO) {
                    adr = uAl + (uint32_t)(((a_row + t * 16) * APAD + ks * 16 + a_col) * 2);
                    LDSM4(al[t], adr);
                }
            }
#pragma unroll
            for (int jn = 0; jn < 4; jn++) {
                uint32_t bh[4];
                uint32_t badr = uB + (uint32_t)(((ks * 16 + b_row) * BPAD + b_col + jn * 16) * 2);
                LDSM4T(bh, badr);
                MMA16816(acc[0][jn * 2],     ah[0], bh[0], bh[1]);
                MMA16816(acc[1][jn * 2],     ah[1], bh[0], bh[1]);
                MMA16816(acc[0][jn * 2 + 1], ah[0], bh[2], bh[3]);
                MMA16816(acc[1][jn * 2 + 1], ah[1], bh[2], bh[3]);
                if (LO) {
                    MMA16816(acc[0][jn * 2],     al[0], bh[0], bh[1]);
                    MMA16816(acc[1][jn * 2],     al[1], bh[0], bh[1]);
                    MMA16816(acc[0][jn * 2 + 1], al[0], bh[2], bh[3]);
                    MMA16816(acc[1][jn * 2 + 1], al[1], bh[2], bh[3]);
                }
            }
        }
    }

    // ---- epilogue: store (fp16 y0 | fp32 out) + fused per-channel stats ----
    const int gr = lane >> 2, qc = (lane & 3) * 2;
#pragma unroll
    for (int t = 0; t < 2; t++) {
        int ch0 = m0 + wm + t * 16 + gr;          // rows ch0 and ch0+8
        float s0 = 0.f, q0 = 0.f, s1 = 0.f, q1 = 0.f;
        size_t col = (size_t)n0 + wn + qc;
#pragma unroll
        for (int j = 0; j < 8; j++) {
            float2 v = {acc[t][j][0], acc[t][j][1]};
            float2 w = {acc[t][j][2], acc[t][j][3]};
            s0 += v.x + v.y; q0 += v.x * v.x + v.y * v.y;
            s1 += w.x + w.y; q1 += w.x * w.x + w.y * w.y;
            if (WHICH) {
                float* p0 = outp + ((size_t)b * 256 + ch0) * Npts + col + j * 8;
                *(float2*)p0 = v;
                *(float2*)(p0 + 8 * (size_t)Npts) = w;
            } else {
                __half* p0 = g_y0h + ((size_t)b * 256 + ch0) * Npts + col + j * 8;
                *(__half2*)p0 = __floats2half2_rn(v.x, v.y);
                *(__half2*)(p0 + 8 * (size_t)Npts) = __floats2half2_rn(w.x, w.y);
            }
        }
#pragma unroll
        for (int o = 1; o < 4; o <<= 1) {
            s0 += __shfl_xor_sync(0xffffffffu, s0, o);
            q0 += __shfl_xor_sync(0xffffffffu, q0, o);
            s1 += __shfl_xor_sync(0xffffffffu, s1, o);
            q1 += __shfl_xor_sync(0xffffffffu, q1, o);
        }
        if ((lane & 3) == 0) {
            atomicAdd(sum + ch0, s0);      atomicAdd(sq + ch0, q0);
            atomicAdd(sum + ch0 + 8, s1);  atomicAdd(sq + ch0 + 8, q1);
        }
    }
}

// ---------------- final BN2 + ReLU in place on d_out ----------------
__global__ void bnrelu_kernel(float* __restrict__ out) {
    size_t i = (size_t)blockIdx.x * 256 + threadIdx.x;   // float4 index
    int c = (int)((i / (Npts / 4)) & (COUT - 1));
    float a = g_a1[c], be = g_be1[c];
    float4 v = ((float4*)out)[i];
    v.x = fmaxf(fmaf(a, v.x, be), 0.f);
    v.y = fmaxf(fmaf(a, v.y, be), 0.f);
    v.z = fmaxf(fmaf(a, v.z, be), 0.f);
    v.w = fmaxf(fmaf(a, v.w, be), 0.f);
    ((float4*)out)[i] = v;
}

// ---------------- launch ----------------
extern "C" void kernel_launch(void* const* d_in, const int* in_sizes, int n_in,
                              void* d_out, int out_size) {
    const float* xyz1    = (const float*)d_in[0];
    const float* xyz2    = (const float*)d_in[1];
    const float* points1 = (const float*)d_in[2];
    const float* points2 = (const float*)d_in[3];
    const float* w0      = (const float*)d_in[4];
    const float* g0      = (const float*)d_in[6];
    const float* be0     = (const float*)d_in[7];
    const float* w1      = (const float*)d_in[8];
    const float* g1      = (const float*)d_in[10];
    const float* be1     = (const float*)d_in[11];
    float* out = (float*)d_out;

    split_w0_kernel<<<(CMID * CIN + 255) / 256, 256>>>(w0);
    split_w1_kernel<<<(COUT * CMID + 255) / 256, 256>>>(w1);
    transpose_p2_kernel<<<dim3(Spts / 32, Dfeat / 32, Bsz), dim3(32, 8)>>>(points2);
    knn_kernel<<<dim3(Npts / 256, Bsz), 256>>>(xyz1, xyz2);
    interp_kernel<<<dim3(Npts / 32, Bsz), 256>>>();
    zero_stats_kernel<<<1, 256>>>();
    gemm_mma_kernel<0, false><<<dim3(2, Npts / 128, Bsz), 256>>>(points1, nullptr, out);
    finalize0_kernel<<<1, CMID>>>(g0, be0);
    gemm_mma_kernel<1, false><<<dim3(2, Npts / 128, Bsz), 256>>>(points1, nullptr, out);
    finalize1_kernel<<<1, COUT>>>(g1, be1);
    bnrelu_kernel<<<(int)(((size_t)Bsz * COUT * Npts / 4) / 256), 256>>>(out);
}